// round 6
// baseline (speedup 1.0000x reference)
#include <cuda_runtime.h>
#include <math.h>
#include <float.h>
#include <stdint.h>

#define BB      64
#define TT      100
#define NN      20000
#define NCH     32
#define CHUNK_REAL 625
#define CHUNK_PAD  640
#define NPAIR   (CHUNK_PAD / 2)       // 320 pairs per CTA
#define THREADS 256
#define WARPS   8
#define SUBPAIR (NPAIR / WARPS)       // 40 pairs per warp (80 points)
#define SEGPAIR 8                     // pairs per segment (16 points)
#define NSEG    (SUBPAIR / SEGPAIR)   // 5
#define NSUB    NCH                   // 32 partials per (b,t) after CTA reduce
#define NTB     (TT / 4)              // 25 t-blocks in reduce kernel

// Scratch (no allocation allowed in kernel_launch)
__device__ float g_pmin[BB * TT * NSUB];
__device__ int   g_pidx[BB * TT * NSUB];
__device__ float g_part[BB * NTB];

// ---- packed f32x2 helpers -------------------------------------------------
__device__ __forceinline__ uint64_t ffma2(uint64_t a, uint64_t b, uint64_t c) {
    uint64_t d;
    asm("fma.rn.f32x2 %0, %1, %2, %3;" : "=l"(d) : "l"(a), "l"(b), "l"(c));
    return d;
}
__device__ __forceinline__ uint64_t pack2(float v) {
    uint64_t r;
    asm("mov.b64 %0, {%1, %1};" : "=l"(r) : "f"(v));
    return r;
}
__device__ __forceinline__ void unpack2(float& lo, float& hi, uint64_t v) {
    asm("mov.b64 {%0, %1}, %2;" : "=f"(lo), "=f"(hi) : "l"(v));
}
__device__ __forceinline__ void lds_v2b64(uint64_t& a, uint64_t& b, uint32_t addr) {
    asm volatile("ld.shared.v2.b64 {%0, %1}, [%2];" : "=l"(a), "=l"(b) : "r"(addr));
}
__device__ __forceinline__ uint32_t smem_u32(const void* p) {
    uint32_t a;
    asm("{ .reg .u64 t; cvta.to.shared.u64 t, %1; cvt.u32.u64 %0, t; }"
        : "=r"(a) : "l"(p));
    return a;
}

// ---------------------------------------------------------------------------
// Kernel 1: CTA = (chunk, b), 8 warps. Transform 625-pt chunk into local frame
// once (pair-interleaved SMEM: [x0x1 y0y1 z0z1 c0c1], c = 0.5*|p|^2).
// Each warp scans 40 pairs for 4 waypoint slots per lane with packed FFMA2;
// running min kept as TWO independent scalar FMNMX chains per slot (lo/hi
// register halves of the packed result — unpack is a free register alias).
// Segment-level min (16 pts) + exact-equality rescan recovers the index.
// Cross-warp SMEM reduce -> NCH=32 partials per (b,t).
// ---------------------------------------------------------------------------
__global__ void __launch_bounds__(THREADS, 4) nn_kernel(
    const float* __restrict__ poses,     // [B,4,4] row-major
    const float* __restrict__ wpts,      // [B,T,3]
    const float* __restrict__ boundary)  // [4,N]
{
    __shared__ uint64_t pts[NPAIR * 4];    // 10240 B
    __shared__ float    red_q[WARPS][128]; // 4 KB
    __shared__ int      red_i[WARPS][128]; // 4 KB

    const int ch  = blockIdx.x;
    const int b   = blockIdx.y;
    const int tid = threadIdx.x;

    // SE(3) inverse: p_local = R^T (p_global - t)
    const float* P = poses + b * 16;
    const float r00 = P[0], r01 = P[1], r02 = P[2],  tx = P[3];
    const float r10 = P[4], r11 = P[5], r12 = P[6],  ty = P[7];
    const float r20 = P[8], r21 = P[9], r22 = P[10], tz = P[11];

    const int gbase = ch * CHUNK_REAL;
    float* fpts = (float*)pts;
    for (int i = tid; i < CHUNK_PAD; i += THREADS) {
        float lx = 0.0f, ly = 0.0f, lz = 0.0f, c = 1e30f;  // pad: never wins
        if (i < CHUNK_REAL) {
            float px = boundary[0 * NN + gbase + i];
            float py = boundary[1 * NN + gbase + i];
            float pz = boundary[2 * NN + gbase + i];
            float dx = px - tx, dy = py - ty, dz = pz - tz;
            lx = fmaf(r00, dx, fmaf(r10, dy, r20 * dz));
            ly = fmaf(r01, dx, fmaf(r11, dy, r21 * dz));
            lz = fmaf(r02, dx, fmaf(r12, dy, r22 * dz));
            c  = 0.5f * fmaf(lx, lx, fmaf(ly, ly, lz * lz));
        }
        int m = i >> 1, h = i & 1;
        fpts[m * 8 + 0 + h] = lx;
        fpts[m * 8 + 2 + h] = ly;
        fpts[m * 8 + 4 + h] = lz;
        fpts[m * 8 + 6 + h] = c;
    }
    __syncthreads();

    const int warp = tid >> 5;
    const int lane = tid & 31;

    // 4 waypoint slots per lane (slots >= TT duplicate t=TT-1, never used)
    uint64_t nwx2[4], nwy2[4], nwz2[4];
    #pragma unroll
    for (int j = 0; j < 4; ++j) {
        int sl = lane + 32 * j;
        int t = (sl < TT) ? sl : (TT - 1);
        const float* w = wpts + (b * TT + t) * 3;
        nwx2[j] = pack2(-w[0]);
        nwy2[j] = pack2(-w[1]);
        nwz2[j] = pack2(-w[2]);
    }

    float best[4];
    int   sid[4];
    #pragma unroll
    for (int j = 0; j < 4; ++j) { best[j] = FLT_MAX; sid[j] = 0; }

    const uint32_t wbase = smem_u32(pts) + (uint32_t)(warp * SUBPAIR) * 32u;

    #pragma unroll
    for (int s = 0; s < NSEG; ++s) {
        const uint32_t segb = wbase + (uint32_t)(s * SEGPAIR) * 32u;
        float svlo[4], svhi[4];
        #pragma unroll
        for (int j = 0; j < 4; ++j) { svlo[j] = FLT_MAX; svhi[j] = FLT_MAX; }

        #pragma unroll 4
        for (int pp = 0; pp < SEGPAIR; ++pp) {
            uint64_t xx, yy, zz, cc;
            lds_v2b64(xx, yy, segb + pp * 32u);        // broadcast, conflict-free
            lds_v2b64(zz, cc, segb + pp * 32u + 16u);
            #pragma unroll
            for (int j = 0; j < 4; ++j) {
                uint64_t q = ffma2(nwx2[j], xx,
                             ffma2(nwy2[j], yy,
                             ffma2(nwz2[j], zz, cc)));
                float qlo, qhi;
                unpack2(qlo, qhi, q);                  // register alias, free
                svlo[j] = fminf(svlo[j], qlo);         // two independent chains
                svhi[j] = fminf(svhi[j], qhi);
            }
        }
        #pragma unroll
        for (int j = 0; j < 4; ++j) {
            float m = fminf(svlo[j], svhi[j]);
            sid[j]  = (m < best[j]) ? s : sid[j];
            best[j] = fminf(best[j], m);
        }
    }

    // Rescan winning 16-pt segment; scalar fmaf chain matches per-element
    // fma.rn.f32x2 exactly, so equality recovery is exact (first hit wins).
    const float* f = (const float*)pts;
    #pragma unroll
    for (int j = 0; j < 4; ++j) {
        float nwx, nwy, nwz, dmy;
        unpack2(nwx, dmy, nwx2[j]);
        unpack2(nwy, dmy, nwy2[j]);
        unpack2(nwz, dmy, nwz2[j]);
        const int pbase = warp * SUBPAIR * 2 + sid[j] * SEGPAIR * 2;
        int loc = -1;
        #pragma unroll
        for (int k = 0; k < SEGPAIR * 2; ++k) {
            int p = pbase + k, m = p >> 1, h = p & 1;
            float q = fmaf(nwx, f[m * 8 + 0 + h],
                      fmaf(nwy, f[m * 8 + 2 + h],
                      fmaf(nwz, f[m * 8 + 4 + h], f[m * 8 + 6 + h])));
            if (q == best[j] && loc < 0) loc = k;
        }
        if (loc < 0) loc = 0;  // unreachable safety
        red_q[warp][lane + 32 * j] = best[j];
        red_i[warp][lane + 32 * j] = gbase + pbase + loc;
    }
    __syncthreads();

    // Cross-warp reduce: thread = slot; strict < keeps lowest warp = lowest idx.
    if (tid < 128) {
        float bq = red_q[0][tid];
        int   bi = red_i[0][tid];
        #pragma unroll
        for (int w = 1; w < WARPS; ++w) {
            float q = red_q[w][tid];
            int   i = red_i[w][tid];
            if (q < bq) { bq = q; bi = i; }
        }
        if (tid < TT) {
            const int o = (b * TT + tid) * NSUB + ch;
            g_pmin[o] = bq;
            g_pidx[o] = bi;
        }
    }
}

// ---------------------------------------------------------------------------
// Kernel 2: warp per (b,t). Lane s reads partial s (NSUB=32 -> exactly one
// warp). Shuffle-argmin (tie-break: lowest global index), lane 0 fetches the
// winning point + normal, transforms, dots, ExpRelu; CTA sums its 4 t-values.
// ---------------------------------------------------------------------------
__global__ void __launch_bounds__(128) reduce_kernel(
    const float* __restrict__ poses,
    const float* __restrict__ wpts,
    const float* __restrict__ boundary,
    const float* __restrict__ nrms)      // [3,N]
{
    const int b    = blockIdx.x;
    const int warp = threadIdx.x >> 5;
    const int lane = threadIdx.x & 31;
    const int t    = blockIdx.y * 4 + warp;

    const int o = (b * TT + t) * NSUB + lane;
    float q = g_pmin[o];
    int   i = g_pidx[o];
    #pragma unroll
    for (int off = 16; off > 0; off >>= 1) {
        float q2 = __shfl_xor_sync(0xFFFFFFFFu, q, off);
        int   i2 = __shfl_xor_sync(0xFFFFFFFFu, i, off);
        if (q2 < q || (q2 == q && i2 < i)) { q = q2; i = i2; }
    }

    __shared__ float sh[4];
    if (lane == 0) {
        const float* P = poses + b * 16;
        const float r00 = P[0], r01 = P[1], r02 = P[2],  tx = P[3];
        const float r10 = P[4], r11 = P[5], r12 = P[6],  ty = P[7];
        const float r20 = P[8], r21 = P[9], r22 = P[10], tz = P[11];

        float px = boundary[0 * NN + i];
        float py = boundary[1 * NN + i];
        float pz = boundary[2 * NN + i];
        float dx = px - tx, dy = py - ty, dz = pz - tz;
        float cpx = fmaf(r00, dx, fmaf(r10, dy, r20 * dz));
        float cpy = fmaf(r01, dx, fmaf(r11, dy, r21 * dz));
        float cpz = fmaf(r02, dx, fmaf(r12, dy, r22 * dz));

        float nx = nrms[0 * NN + i];
        float ny = nrms[1 * NN + i];
        float nz = nrms[2 * NN + i];
        float cnx = fmaf(r00, nx, fmaf(r10, ny, r20 * nz));
        float cny = fmaf(r01, nx, fmaf(r11, ny, r21 * nz));
        float cnz = fmaf(r02, nx, fmaf(r12, ny, r22 * nz));

        const float* w = wpts + (b * TT + t) * 3;
        float d = (w[0] - cpx) * cnx + (w[1] - cpy) * cny + (w[2] - cpz) * cnz;

        sh[warp] = (d > 0.0f) ? (d + 1.0f) : expf(0.5f * d);  // ExpRelu a=1,b=.5
    }
    __syncthreads();
    if (threadIdx.x == 0)
        g_part[b * NTB + blockIdx.y] = sh[0] + sh[1] + sh[2] + sh[3];
}

// ---------------------------------------------------------------------------
// Kernel 3: one CTA sums BB*NTB = 1600 partials -> scalar loss. Deterministic.
// ---------------------------------------------------------------------------
__global__ void __launch_bounds__(256) final_kernel(float* __restrict__ out)
{
    const int tid = threadIdx.x;
    float s = 0.0f;
    for (int k = tid; k < BB * NTB; k += 256) s += g_part[k];
    __shared__ float sh[256];
    sh[tid] = s;
    __syncthreads();
    #pragma unroll
    for (int o = 128; o > 0; o >>= 1) {
        if (tid < o) sh[tid] += sh[tid + o];
        __syncthreads();
    }
    if (tid == 0) out[0] = sh[0] * (1.0f / (float)(BB * TT));
}

// ---------------------------------------------------------------------------
extern "C" void kernel_launch(void* const* d_in, const int* in_sizes, int n_in,
                              void* d_out, int out_size)
{
    const float* poses    = (const float*)d_in[0];  // [64,4,4]
    const float* wpts     = (const float*)d_in[1];  // [64,100,3]
    const float* boundary = (const float*)d_in[2];  // [4,20000]
    const float* nrms     = (const float*)d_in[3];  // [3,20000]
    float* out = (float*)d_out;

    dim3 grid1(NCH, BB);
    nn_kernel<<<grid1, THREADS>>>(poses, wpts, boundary);
    dim3 grid2(BB, NTB);
    reduce_kernel<<<grid2, 128>>>(poses, wpts, boundary, nrms);
    final_kernel<<<1, 256>>>(out);
}

// round 7
// speedup vs baseline: 1.5765x; 1.5765x over previous
#include <cuda_runtime.h>
#include <math.h>
#include <float.h>
#include <stdint.h>

#define BB      64
#define TT      100
#define NN      20000
#define NCH     32
#define CHUNK_REAL 625
#define CHUNK_PAD  640
#define NPAIR   (CHUNK_PAD / 2)       // 320 pairs per CTA
#define THREADS 256
#define WARPS   8
#define SUBPAIR (NPAIR / WARPS)       // 40 pairs per warp (80 points)
#define SEGPAIR 8                     // pairs per segment (16 points)
#define NSEG    (SUBPAIR / SEGPAIR)   // 5
#define NSUB    NCH                   // 32 partials per (b,t) after CTA reduce
#define NTB     (TT / 4)              // 25 t-blocks in reduce kernel

// Scratch (no allocation allowed in kernel_launch)
__device__ float g_pmin[BB * TT * NSUB];
__device__ int   g_pidx[BB * TT * NSUB];
__device__ float g_part[BB * NTB];

// ---- packed f32x2 helpers -------------------------------------------------
__device__ __forceinline__ uint64_t ffma2(uint64_t a, uint64_t b, uint64_t c) {
    uint64_t d;
    asm("fma.rn.f32x2 %0, %1, %2, %3;" : "=l"(d) : "l"(a), "l"(b), "l"(c));
    return d;
}
__device__ __forceinline__ uint64_t pack2(float v) {
    uint64_t r;
    asm("mov.b64 %0, {%1, %1};" : "=l"(r) : "f"(v));
    return r;
}
__device__ __forceinline__ void unpack2(float& lo, float& hi, uint64_t v) {
    asm("mov.b64 {%0, %1}, %2;" : "=f"(lo), "=f"(hi) : "l"(v));
}
__device__ __forceinline__ void lds_v2b64(uint64_t& a, uint64_t& b, uint32_t addr) {
    asm volatile("ld.shared.v2.b64 {%0, %1}, [%2];" : "=l"(a), "=l"(b) : "r"(addr));
}
__device__ __forceinline__ uint32_t smem_u32(const void* p) {
    uint32_t a;
    asm("{ .reg .u64 t; cvta.to.shared.u64 t, %1; cvt.u32.u64 %0, t; }"
        : "=r"(a) : "l"(p));
    return a;
}

// ---------------------------------------------------------------------------
// Kernel 1: CTA = (chunk, b), 8 warps. Transform 625-pt chunk into local frame
// once (pair-interleaved SMEM: [x0x1 y0y1 z0z1 c0c1], c = 0.5*|p|^2).
// Each warp scans 40 pairs for 4 waypoint slots per lane with packed FFMA2;
// running min kept as TWO independent scalar FMNMX chains per slot (lo/hi
// register halves of the packed result — unpack is a free register alias).
// Segment-level min (16 pts) + exact-equality rescan recovers the index.
// Cross-warp SMEM reduce -> NCH=32 partials per (b,t).
// ---------------------------------------------------------------------------
__global__ void __launch_bounds__(THREADS, 4) nn_kernel(
    const float* __restrict__ poses,     // [B,4,4] row-major
    const float* __restrict__ wpts,      // [B,T,3]
    const float* __restrict__ boundary)  // [4,N]
{
    __shared__ uint64_t pts[NPAIR * 4];    // 10240 B
    __shared__ float    red_q[WARPS][128]; // 4 KB
    __shared__ int      red_i[WARPS][128]; // 4 KB

    const int ch  = blockIdx.x;
    const int b   = blockIdx.y;
    const int tid = threadIdx.x;

    // SE(3) inverse: p_local = R^T (p_global - t)
    const float* P = poses + b * 16;
    const float r00 = P[0], r01 = P[1], r02 = P[2],  tx = P[3];
    const float r10 = P[4], r11 = P[5], r12 = P[6],  ty = P[7];
    const float r20 = P[8], r21 = P[9], r22 = P[10], tz = P[11];

    const int gbase = ch * CHUNK_REAL;
    float* fpts = (float*)pts;
    for (int i = tid; i < CHUNK_PAD; i += THREADS) {
        float lx = 0.0f, ly = 0.0f, lz = 0.0f, c = 1e30f;  // pad: never wins
        if (i < CHUNK_REAL) {
            float px = boundary[0 * NN + gbase + i];
            float py = boundary[1 * NN + gbase + i];
            float pz = boundary[2 * NN + gbase + i];
            float dx = px - tx, dy = py - ty, dz = pz - tz;
            lx = fmaf(r00, dx, fmaf(r10, dy, r20 * dz));
            ly = fmaf(r01, dx, fmaf(r11, dy, r21 * dz));
            lz = fmaf(r02, dx, fmaf(r12, dy, r22 * dz));
            c  = 0.5f * fmaf(lx, lx, fmaf(ly, ly, lz * lz));
        }
        int m = i >> 1, h = i & 1;
        fpts[m * 8 + 0 + h] = lx;
        fpts[m * 8 + 2 + h] = ly;
        fpts[m * 8 + 4 + h] = lz;
        fpts[m * 8 + 6 + h] = c;
    }
    __syncthreads();

    const int warp = tid >> 5;
    const int lane = tid & 31;

    // 4 waypoint slots per lane (slots >= TT duplicate t=TT-1, never used)
    uint64_t nwx2[4], nwy2[4], nwz2[4];
    #pragma unroll
    for (int j = 0; j < 4; ++j) {
        int sl = lane + 32 * j;
        int t = (sl < TT) ? sl : (TT - 1);
        const float* w = wpts + (b * TT + t) * 3;
        nwx2[j] = pack2(-w[0]);
        nwy2[j] = pack2(-w[1]);
        nwz2[j] = pack2(-w[2]);
    }

    float best[4];
    int   sid[4];
    #pragma unroll
    for (int j = 0; j < 4; ++j) { best[j] = FLT_MAX; sid[j] = 0; }

    const uint32_t wbase = smem_u32(pts) + (uint32_t)(warp * SUBPAIR) * 32u;

    #pragma unroll
    for (int s = 0; s < NSEG; ++s) {
        const uint32_t segb = wbase + (uint32_t)(s * SEGPAIR) * 32u;
        float svlo[4], svhi[4];
        #pragma unroll
        for (int j = 0; j < 4; ++j) { svlo[j] = FLT_MAX; svhi[j] = FLT_MAX; }

        #pragma unroll 4
        for (int pp = 0; pp < SEGPAIR; ++pp) {
            uint64_t xx, yy, zz, cc;
            lds_v2b64(xx, yy, segb + pp * 32u);        // broadcast, conflict-free
            lds_v2b64(zz, cc, segb + pp * 32u + 16u);
            #pragma unroll
            for (int j = 0; j < 4; ++j) {
                uint64_t q = ffma2(nwx2[j], xx,
                             ffma2(nwy2[j], yy,
                             ffma2(nwz2[j], zz, cc)));
                float qlo, qhi;
                unpack2(qlo, qhi, q);                  // register alias, free
                svlo[j] = fminf(svlo[j], qlo);         // two independent chains
                svhi[j] = fminf(svhi[j], qhi);
            }
        }
        #pragma unroll
        for (int j = 0; j < 4; ++j) {
            float m = fminf(svlo[j], svhi[j]);
            sid[j]  = (m < best[j]) ? s : sid[j];
            best[j] = fminf(best[j], m);
        }
    }

    // Rescan winning 16-pt segment; scalar fmaf chain matches per-element
    // fma.rn.f32x2 exactly, so equality recovery is exact (first hit wins).
    const float* f = (const float*)pts;
    #pragma unroll
    for (int j = 0; j < 4; ++j) {
        float nwx, nwy, nwz, dmy;
        unpack2(nwx, dmy, nwx2[j]);
        unpack2(nwy, dmy, nwy2[j]);
        unpack2(nwz, dmy, nwz2[j]);
        const int pbase = warp * SUBPAIR * 2 + sid[j] * SEGPAIR * 2;
        int loc = -1;
        #pragma unroll
        for (int k = 0; k < SEGPAIR * 2; ++k) {
            int p = pbase + k, m = p >> 1, h = p & 1;
            float q = fmaf(nwx, f[m * 8 + 0 + h],
                      fmaf(nwy, f[m * 8 + 2 + h],
                      fmaf(nwz, f[m * 8 + 4 + h], f[m * 8 + 6 + h])));
            if (q == best[j] && loc < 0) loc = k;
        }
        if (loc < 0) loc = 0;  // unreachable safety
        red_q[warp][lane + 32 * j] = best[j];
        red_i[warp][lane + 32 * j] = gbase + pbase + loc;
    }
    __syncthreads();

    // Cross-warp reduce: thread = slot; strict < keeps lowest warp = lowest idx.
    if (tid < 128) {
        float bq = red_q[0][tid];
        int   bi = red_i[0][tid];
        #pragma unroll
        for (int w = 1; w < WARPS; ++w) {
            float q = red_q[w][tid];
            int   i = red_i[w][tid];
            if (q < bq) { bq = q; bi = i; }
        }
        if (tid < TT) {
            const int o = (b * TT + tid) * NSUB + ch;
            g_pmin[o] = bq;
            g_pidx[o] = bi;
        }
    }
}

// ---------------------------------------------------------------------------
// Kernel 2: warp per (b,t). Lane s reads partial s (NSUB=32 -> exactly one
// warp). Shuffle-argmin (tie-break: lowest global index), lane 0 fetches the
// winning point + normal, transforms, dots, ExpRelu; CTA sums its 4 t-values.
// ---------------------------------------------------------------------------
__global__ void __launch_bounds__(128) reduce_kernel(
    const float* __restrict__ poses,
    const float* __restrict__ wpts,
    const float* __restrict__ boundary,
    const float* __restrict__ nrms)      // [3,N]
{
    const int b    = blockIdx.x;
    const int warp = threadIdx.x >> 5;
    const int lane = threadIdx.x & 31;
    const int t    = blockIdx.y * 4 + warp;

    const int o = (b * TT + t) * NSUB + lane;
    float q = g_pmin[o];
    int   i = g_pidx[o];
    #pragma unroll
    for (int off = 16; off > 0; off >>= 1) {
        float q2 = __shfl_xor_sync(0xFFFFFFFFu, q, off);
        int   i2 = __shfl_xor_sync(0xFFFFFFFFu, i, off);
        if (q2 < q || (q2 == q && i2 < i)) { q = q2; i = i2; }
    }

    __shared__ float sh[4];
    if (lane == 0) {
        const float* P = poses + b * 16;
        const float r00 = P[0], r01 = P[1], r02 = P[2],  tx = P[3];
        const float r10 = P[4], r11 = P[5], r12 = P[6],  ty = P[7];
        const float r20 = P[8], r21 = P[9], r22 = P[10], tz = P[11];

        float px = boundary[0 * NN + i];
        float py = boundary[1 * NN + i];
        float pz = boundary[2 * NN + i];
        float dx = px - tx, dy = py - ty, dz = pz - tz;
        float cpx = fmaf(r00, dx, fmaf(r10, dy, r20 * dz));
        float cpy = fmaf(r01, dx, fmaf(r11, dy, r21 * dz));
        float cpz = fmaf(r02, dx, fmaf(r12, dy, r22 * dz));

        float nx = nrms[0 * NN + i];
        float ny = nrms[1 * NN + i];
        float nz = nrms[2 * NN + i];
        float cnx = fmaf(r00, nx, fmaf(r10, ny, r20 * nz));
        float cny = fmaf(r01, nx, fmaf(r11, ny, r21 * nz));
        float cnz = fmaf(r02, nx, fmaf(r12, ny, r22 * nz));

        const float* w = wpts + (b * TT + t) * 3;
        float d = (w[0] - cpx) * cnx + (w[1] - cpy) * cny + (w[2] - cpz) * cnz;

        sh[warp] = (d > 0.0f) ? (d + 1.0f) : expf(0.5f * d);  // ExpRelu a=1,b=.5
    }
    __syncthreads();
    if (threadIdx.x == 0)
        g_part[b * NTB + blockIdx.y] = sh[0] + sh[1] + sh[2] + sh[3];
}

// ---------------------------------------------------------------------------
// Kernel 3: one CTA sums BB*NTB = 1600 partials -> scalar loss. Deterministic.
// ---------------------------------------------------------------------------
__global__ void __launch_bounds__(256) final_kernel(float* __restrict__ out)
{
    const int tid = threadIdx.x;
    float s = 0.0f;
    for (int k = tid; k < BB * NTB; k += 256) s += g_part[k];
    __shared__ float sh[256];
    sh[tid] = s;
    __syncthreads();
    #pragma unroll
    for (int o = 128; o > 0; o >>= 1) {
        if (tid < o) sh[tid] += sh[tid + o];
        __syncthreads();
    }
    if (tid == 0) out[0] = sh[0] * (1.0f / (float)(BB * TT));
}

// ---------------------------------------------------------------------------
extern "C" void kernel_launch(void* const* d_in, const int* in_sizes, int n_in,
                              void* d_out, int out_size)
{
    const float* poses    = (const float*)d_in[0];  // [64,4,4]
    const float* wpts     = (const float*)d_in[1];  // [64,100,3]
    const float* boundary = (const float*)d_in[2];  // [4,20000]
    const float* nrms     = (const float*)d_in[3];  // [3,20000]
    float* out = (float*)d_out;

    dim3 grid1(NCH, BB);
    nn_kernel<<<grid1, THREADS>>>(poses, wpts, boundary);
    dim3 grid2(BB, NTB);
    reduce_kernel<<<grid2, 128>>>(poses, wpts, boundary, nrms);
    final_kernel<<<1, 256>>>(out);
}

// round 8
// speedup vs baseline: 3.1155x; 1.9761x over previous
#include <cuda_runtime.h>
#include <math.h>
#include <float.h>
#include <stdint.h>

#define BB      64
#define TT      100
#define NQ      (BB * TT)          // 6400 queries (flat)
#define NN      20000
#define NCH     16
#define CH_PTS  1250               // real points per chunk
#define CH_PAD  1280               // padded points per chunk
#define CH_PAIR 640                // pairs per chunk
#define WARPS   8
#define WPAIR   (CH_PAIR / WARPS)  // 80 pairs per warp
#define RANGE   (WPAIR * 2)        // 160 points per warp range
#define NTILE   (NQ / 128)         // 50 query tiles
#define THREADS 256

// Scratch (no allocation allowed in kernel_launch)
// Pair-interleaved global point tile: pair m -> float4{x0,x1,y0,y1}, float4{z0,z1,c0,c1}
__device__ float4 g_pts[NCH * CH_PAIR * 2];     // 327 KB, L2-resident
__device__ float  g_wqx[NQ], g_wqy[NQ], g_wqz[NQ];  // NEGATED global waypoints
__device__ float  g_pmin[NQ * NCH];
__device__ int    g_ps0 [NQ * NCH];             // padded-index start of winning 160-pt range
__device__ float  g_part[NQ / 8];

// ---- packed f32x2 helpers -------------------------------------------------
__device__ __forceinline__ uint64_t ffma2(uint64_t a, uint64_t b, uint64_t c) {
    uint64_t d;
    asm("fma.rn.f32x2 %0, %1, %2, %3;" : "=l"(d) : "l"(a), "l"(b), "l"(c));
    return d;
}
__device__ __forceinline__ uint64_t pack2(float v) {
    uint64_t r;
    asm("mov.b64 %0, {%1, %1};" : "=l"(r) : "f"(v));
    return r;
}
__device__ __forceinline__ void unpack2(float& lo, float& hi, uint64_t v) {
    asm("mov.b64 {%0, %1}, %2;" : "=f"(lo), "=f"(hi) : "l"(v));
}
__device__ __forceinline__ void lds_v2b64(uint64_t& a, uint64_t& b, uint32_t addr) {
    asm volatile("ld.shared.v2.b64 {%0, %1}, [%2];" : "=l"(a), "=l"(b) : "r"(addr));
}
__device__ __forceinline__ uint32_t smem_u32(const void* p) {
    uint32_t a;
    asm("{ .reg .u64 t; cvta.to.shared.u64 t, %1; cvt.u32.u64 %0, t; }"
        : "=r"(a) : "l"(p));
    return a;
}

// ---------------------------------------------------------------------------
// Prep: (a) waypoints -> global frame, negated (q = 0.5|p|^2 + nw.p);
//       (b) boundary points -> pair-interleaved (x,y,z,0.5|p|^2) tile, padded.
// ---------------------------------------------------------------------------
__global__ void __launch_bounds__(THREADS) prep_kernel(
    const float* __restrict__ poses,     // [B,4,4] row-major
    const float* __restrict__ wpts,      // [B,T,3] local
    const float* __restrict__ boundary)  // [4,N]
{
    const int gid = blockIdx.x * THREADS + threadIdx.x;
    if (gid < NQ) {
        const int b = gid / TT;
        const float* P = poses + b * 16;
        const float* w = wpts + gid * 3;
        const float wx = w[0], wy = w[1], wz = w[2];
        // forward pose: wg = R*w + t  (exact, no inverse needed)
        float gx = fmaf(P[0], wx, fmaf(P[1], wy, fmaf(P[2],  wz, P[3])));
        float gy = fmaf(P[4], wx, fmaf(P[5], wy, fmaf(P[6],  wz, P[7])));
        float gz = fmaf(P[8], wx, fmaf(P[9], wy, fmaf(P[10], wz, P[11])));
        g_wqx[gid] = -gx; g_wqy[gid] = -gy; g_wqz[gid] = -gz;
    } else {
        const int pid = gid - NQ;              // 0 .. NCH*CH_PAD-1 (20480)
        if (pid < NCH * CH_PAD) {
            const int ch  = pid / CH_PAD;
            const int off = pid - ch * CH_PAD;
            float x = 0.0f, y = 0.0f, z = 0.0f, c = 1e30f;   // pad never wins
            if (off < CH_PTS) {
                const int n = ch * CH_PTS + off;
                x = boundary[0 * NN + n];
                y = boundary[1 * NN + n];
                z = boundary[2 * NN + n];
                c = 0.5f * fmaf(x, x, fmaf(y, y, z * z));
            }
            float* f = (float*)g_pts;
            const int m = pid >> 1, h = pid & 1;
            f[m * 8 + 0 + h] = x;
            f[m * 8 + 2 + h] = y;
            f[m * 8 + 4 + h] = z;
            f[m * 8 + 6 + h] = c;
        }
    }
}

// ---------------------------------------------------------------------------
// NN kernel: CTA = (chunk, query-tile). Copy the chunk's precomputed tile to
// SMEM (no transform!). Each warp scans its 80 pairs for 128 query slots
// (4/lane, zero padding: 128*50 = 6400 exactly) with FFMA2 + 2 FMNMX chains.
// NO index tracking, NO rescan — only (min value, warp) survives; the range
// start is reconstructed from the winning warp id. Cross-warp SMEM reduce ->
// one partial per (query, chunk).
// ---------------------------------------------------------------------------
__global__ void __launch_bounds__(THREADS, 4) nn_kernel()
{
    __shared__ float4 s_pts[CH_PAIR * 2];   // 20 KB
    __shared__ float  red_q[WARPS][128];    // 4 KB

    const int ch   = blockIdx.x;
    const int tile = blockIdx.y;
    const int tid  = threadIdx.x;

    // Copy chunk tile (no math)
    {
        const float4* src = g_pts + ch * CH_PAIR * 2;
        #pragma unroll
        for (int i = tid; i < CH_PAIR * 2; i += THREADS)
            s_pts[i] = src[i];
    }
    __syncthreads();

    const int warp = tid >> 5;
    const int lane = tid & 31;

    // 4 query slots per lane, zero waste
    uint64_t nwx2[4], nwy2[4], nwz2[4];
    #pragma unroll
    for (int j = 0; j < 4; ++j) {
        const int q = tile * 128 + lane + 32 * j;
        nwx2[j] = pack2(g_wqx[q]);
        nwy2[j] = pack2(g_wqy[q]);
        nwz2[j] = pack2(g_wqz[q]);
    }

    // 8 independent running-min chains (lo/hi per slot)
    float blo[4], bhi[4];
    #pragma unroll
    for (int j = 0; j < 4; ++j) { blo[j] = FLT_MAX; bhi[j] = FLT_MAX; }

    const uint32_t wbase = smem_u32(s_pts) + (uint32_t)(warp * WPAIR) * 32u;

    #pragma unroll 4
    for (int pp = 0; pp < WPAIR; ++pp) {
        uint64_t xx, yy, zz, cc;
        lds_v2b64(xx, yy, wbase + pp * 32u);        // broadcast, conflict-free
        lds_v2b64(zz, cc, wbase + pp * 32u + 16u);
        #pragma unroll
        for (int j = 0; j < 4; ++j) {
            uint64_t q = ffma2(nwx2[j], xx,
                         ffma2(nwy2[j], yy,
                         ffma2(nwz2[j], zz, cc)));
            float qlo, qhi;
            unpack2(qlo, qhi, q);                   // register alias, free
            blo[j] = fminf(blo[j], qlo);
            bhi[j] = fminf(bhi[j], qhi);
        }
    }

    #pragma unroll
    for (int j = 0; j < 4; ++j)
        red_q[warp][lane + 32 * j] = fminf(blo[j], bhi[j]);
    __syncthreads();

    // Cross-warp reduce; strict < keeps lowest warp = lowest point index.
    if (tid < 128) {
        float bq = red_q[0][tid];
        int   bw = 0;
        #pragma unroll
        for (int w = 1; w < WARPS; ++w) {
            float q = red_q[w][tid];
            if (q < bq) { bq = q; bw = w; }
        }
        const int qid = tile * 128 + tid;
        g_pmin[qid * NCH + ch] = bq;
        g_ps0 [qid * NCH + ch] = ch * CH_PAD + bw * RANGE;
    }
}

// ---------------------------------------------------------------------------
// Reduce: warp per query. Lanes 0-15 argmin the 16 chunk partials (tie ->
// lowest range start = lowest n). Then all 32 lanes rescan the winning 160-pt
// range from the L2-resident global tile (coalesced, exact fma-chain equality,
// first match = lowest n). Dot with the winner's GLOBAL normal (rotation
// cancels), ExpRelu, CTA-sum of its 8 queries.
// ---------------------------------------------------------------------------
__global__ void __launch_bounds__(THREADS) reduce_kernel(
    const float* __restrict__ nrms)      // [3,N] global normals
{
    const int warp = threadIdx.x >> 5;
    const int lane = threadIdx.x & 31;
    const int qid  = blockIdx.x * 8 + warp;

    float vmin = FLT_MAX;
    int   s0   = 0x7FFFFFFF;
    if (lane < NCH) {
        vmin = g_pmin[qid * NCH + lane];
        s0   = g_ps0 [qid * NCH + lane];
    }
    #pragma unroll
    for (int off = 16; off > 0; off >>= 1) {
        float v2 = __shfl_xor_sync(0xFFFFFFFFu, vmin, off);
        int   s2 = __shfl_xor_sync(0xFFFFFFFFu, s0,   off);
        if (v2 < vmin || (v2 == vmin && s2 < s0)) { vmin = v2; s0 = s2; }
    }

    const float nwx = g_wqx[qid], nwy = g_wqy[qid], nwz = g_wqz[qid];
    const float* f  = (const float*)g_pts;

    // Rescan 160-pt range: exact-equality index recovery, lowest p wins.
    int pbest = 0x7FFFFFFF;
    #pragma unroll
    for (int k = lane; k < RANGE; k += 32) {
        const int p = s0 + k, m = p >> 1, h = p & 1;
        float x = f[m * 8 + 0 + h];
        float y = f[m * 8 + 2 + h];
        float z = f[m * 8 + 4 + h];
        float c = f[m * 8 + 6 + h];
        float q = fmaf(nwx, x, fmaf(nwy, y, fmaf(nwz, z, c)));
        if (q == vmin && p < pbest) pbest = p;
    }
    #pragma unroll
    for (int off = 16; off > 0; off >>= 1)
        pbest = min(pbest, __shfl_xor_sync(0xFFFFFFFFu, pbest, off));

    __shared__ float sh[8];
    if (lane == 0) {
        const int ch = s0 / CH_PAD;
        const int n  = ch * CH_PTS + (pbest - ch * CH_PAD);
        const int m  = pbest >> 1, h = pbest & 1;
        const float cpx = f[m * 8 + 0 + h];
        const float cpy = f[m * 8 + 2 + h];
        const float cpz = f[m * 8 + 4 + h];
        const float nx = nrms[0 * NN + n];
        const float ny = nrms[1 * NN + n];
        const float nz = nrms[2 * NN + n];
        // global-frame dot: (wg - cp) . n_g   (rotations cancel)
        const float d = (-nwx - cpx) * nx + (-nwy - cpy) * ny + (-nwz - cpz) * nz;
        sh[warp] = (d > 0.0f) ? (d + 1.0f) : expf(0.5f * d);  // ExpRelu a=1,b=.5
    }
    __syncthreads();
    if (threadIdx.x == 0) {
        float s = 0.0f;
        #pragma unroll
        for (int w = 0; w < 8; ++w) s += sh[w];
        g_part[blockIdx.x] = s;
    }
}

// ---------------------------------------------------------------------------
// Final: one CTA sums NQ/8 = 800 partials -> scalar loss. Deterministic.
// ---------------------------------------------------------------------------
__global__ void __launch_bounds__(256) final_kernel(float* __restrict__ out)
{
    const int tid = threadIdx.x;
    float s = 0.0f;
    for (int k = tid; k < NQ / 8; k += 256) s += g_part[k];
    __shared__ float sh[256];
    sh[tid] = s;
    __syncthreads();
    #pragma unroll
    for (int o = 128; o > 0; o >>= 1) {
        if (tid < o) sh[tid] += sh[tid + o];
        __syncthreads();
    }
    if (tid == 0) out[0] = sh[0] * (1.0f / (float)NQ);
}

// ---------------------------------------------------------------------------
extern "C" void kernel_launch(void* const* d_in, const int* in_sizes, int n_in,
                              void* d_out, int out_size)
{
    const float* poses    = (const float*)d_in[0];  // [64,4,4]
    const float* wpts     = (const float*)d_in[1];  // [64,100,3]
    const float* boundary = (const float*)d_in[2];  // [4,20000]
    const float* nrms     = (const float*)d_in[3];  // [3,20000]
    float* out = (float*)d_out;

    const int prep_items = NQ + NCH * CH_PAD;                   // 26880
    prep_kernel<<<(prep_items + THREADS - 1) / THREADS, THREADS>>>(
        poses, wpts, boundary);
    dim3 gridn(NCH, NTILE);
    nn_kernel<<<gridn, THREADS>>>();
    reduce_kernel<<<NQ / 8, THREADS>>>(nrms);
    final_kernel<<<1, 256>>>(out);
}

// round 9
// speedup vs baseline: 3.1394x; 1.0077x over previous
#include <cuda_runtime.h>
#include <math.h>
#include <float.h>
#include <stdint.h>

#define BB      64
#define TT      100
#define NQ      (BB * TT)          // 6400 queries (flat)
#define NN      20000
#define NCH     16
#define CH_PTS  1250               // real points per chunk
#define CH_PAD  1280               // padded points per chunk
#define CH_PAIR 640                // pairs per chunk
#define WARPS   8
#define WPAIR   (CH_PAIR / WARPS)  // 80 pairs per warp
#define RANGE   (WPAIR * 2)        // 160 points per warp range
#define NTILE   (NQ / 128)         // 50 query tiles
#define THREADS 256
#define NRED    (NQ / 8)           // 800 reduce CTAs

// Scratch (no device allocation allowed)
__device__ float g_pmin[NQ * NCH];
__device__ int   g_ps0 [NQ * NCH];   // padded-index start of winning 160-pt range
__device__ float g_part[NRED];
__device__ int   g_cnt = 0;          // threadfence-reduction counter (reset by last CTA)

// ---- packed f32x2 helpers -------------------------------------------------
__device__ __forceinline__ uint64_t ffma2(uint64_t a, uint64_t b, uint64_t c) {
    uint64_t d;
    asm("fma.rn.f32x2 %0, %1, %2, %3;" : "=l"(d) : "l"(a), "l"(b), "l"(c));
    return d;
}
__device__ __forceinline__ uint64_t pack2(float v) {
    uint64_t r;
    asm("mov.b64 %0, {%1, %1};" : "=l"(r) : "f"(v));
    return r;
}
__device__ __forceinline__ void unpack2(float& lo, float& hi, uint64_t v) {
    asm("mov.b64 {%0, %1}, %2;" : "=f"(lo), "=f"(hi) : "l"(v));
}
__device__ __forceinline__ void lds_v2b64(uint64_t& a, uint64_t& b, uint32_t addr) {
    asm volatile("ld.shared.v2.b64 {%0, %1}, [%2];" : "=l"(a), "=l"(b) : "r"(addr));
}
__device__ __forceinline__ uint32_t smem_u32(const void* p) {
    uint32_t a;
    asm("{ .reg .u64 t; cvta.to.shared.u64 t, %1; cvt.u32.u64 %0, t; }"
        : "=r"(a) : "l"(p));
    return a;
}

// Query transform: local waypoint -> NEGATED global point. Must be the exact
// same fmaf chain in both kernels (bitwise-identical for equality recovery).
__device__ __forceinline__ void query_transform(
    const float* __restrict__ poses, const float* __restrict__ wpts, int qid,
    float& nwx, float& nwy, float& nwz)
{
    const float* P = poses + (qid / TT) * 16;
    const float* w = wpts + qid * 3;
    const float wx = w[0], wy = w[1], wz = w[2];
    nwx = -fmaf(P[0], wx, fmaf(P[1], wy, fmaf(P[2],  wz, P[3])));
    nwy = -fmaf(P[4], wx, fmaf(P[5], wy, fmaf(P[6],  wz, P[7])));
    nwz = -fmaf(P[8], wx, fmaf(P[9], wy, fmaf(P[10], wz, P[11])));
}

// ---------------------------------------------------------------------------
// NN kernel: CTA = (chunk, query-tile), self-contained. Builds the chunk tile
// (x,y,z,0.5|p|^2, pair-interleaved) from boundary and its 128 query
// transforms in SMEM, then each warp scans its 80 pairs for 128 query slots
// (4/lane, zero padding) with FFMA2 + two scalar FMNMX chains per slot.
// Only (min value, warp range) survives; cross-warp SMEM reduce -> one
// partial per (query, chunk).
// ---------------------------------------------------------------------------
__global__ void __launch_bounds__(THREADS, 4) nn_kernel(
    const float* __restrict__ poses,     // [B,4,4]
    const float* __restrict__ wpts,      // [B,T,3]
    const float* __restrict__ boundary)  // [4,N]
{
    __shared__ float s_pts[CH_PAD * 4];     // 20 KB, pair-interleaved
    __shared__ float s_qx[128], s_qy[128], s_qz[128];
    __shared__ float red_q[WARPS][128];     // 4 KB

    const int ch   = blockIdx.x;
    const int tile = blockIdx.y;
    const int tid  = threadIdx.x;

    // Build chunk tile (identical math to reduce's recompute)
    const int gbase = ch * CH_PTS;
    for (int i = tid; i < CH_PAD; i += THREADS) {
        float x = 0.0f, y = 0.0f, z = 0.0f, c = 1e30f;   // pad never wins
        if (i < CH_PTS) {
            x = boundary[0 * NN + gbase + i];
            y = boundary[1 * NN + gbase + i];
            z = boundary[2 * NN + gbase + i];
            c = 0.5f * fmaf(x, x, fmaf(y, y, z * z));
        }
        const int m = i >> 1, h = i & 1;
        s_pts[m * 8 + 0 + h] = x;
        s_pts[m * 8 + 2 + h] = y;
        s_pts[m * 8 + 4 + h] = z;
        s_pts[m * 8 + 6 + h] = c;
    }
    // Build this tile's 128 query transforms
    if (tid < 128) {
        float nwx, nwy, nwz;
        query_transform(poses, wpts, tile * 128 + tid, nwx, nwy, nwz);
        s_qx[tid] = nwx; s_qy[tid] = nwy; s_qz[tid] = nwz;
    }
    __syncthreads();

    const int warp = tid >> 5;
    const int lane = tid & 31;

    uint64_t nwx2[4], nwy2[4], nwz2[4];
    #pragma unroll
    for (int j = 0; j < 4; ++j) {
        const int sl = lane + 32 * j;
        nwx2[j] = pack2(s_qx[sl]);
        nwy2[j] = pack2(s_qy[sl]);
        nwz2[j] = pack2(s_qz[sl]);
    }

    // 8 independent running-min chains (lo/hi per slot)
    float blo[4], bhi[4];
    #pragma unroll
    for (int j = 0; j < 4; ++j) { blo[j] = FLT_MAX; bhi[j] = FLT_MAX; }

    const uint32_t wbase = smem_u32(s_pts) + (uint32_t)(warp * WPAIR) * 32u;

    #pragma unroll 4
    for (int pp = 0; pp < WPAIR; ++pp) {
        uint64_t xx, yy, zz, cc;
        lds_v2b64(xx, yy, wbase + pp * 32u);        // broadcast, conflict-free
        lds_v2b64(zz, cc, wbase + pp * 32u + 16u);
        #pragma unroll
        for (int j = 0; j < 4; ++j) {
            uint64_t q = ffma2(nwx2[j], xx,
                         ffma2(nwy2[j], yy,
                         ffma2(nwz2[j], zz, cc)));
            float qlo, qhi;
            unpack2(qlo, qhi, q);                   // register alias, free
            blo[j] = fminf(blo[j], qlo);
            bhi[j] = fminf(bhi[j], qhi);
        }
    }

    #pragma unroll
    for (int j = 0; j < 4; ++j)
        red_q[warp][lane + 32 * j] = fminf(blo[j], bhi[j]);
    __syncthreads();

    // Cross-warp reduce; strict < keeps lowest warp = lowest point index.
    if (tid < 128) {
        float bq = red_q[0][tid];
        int   bw = 0;
        #pragma unroll
        for (int w = 1; w < WARPS; ++w) {
            float q = red_q[w][tid];
            if (q < bq) { bq = q; bw = w; }
        }
        const int qid = tile * 128 + tid;
        g_pmin[qid * NCH + ch] = bq;
        g_ps0 [qid * NCH + ch] = ch * CH_PAD + bw * RANGE;
    }
}

// ---------------------------------------------------------------------------
// Reduce + final (threadfence reduction): warp per query. 16-partial shuffle
// argmin (tie -> lowest range = lowest n), coalesced 160-pt rescan recomputing
// the bitwise-identical fma chain from boundary, dot with global normal
// (rotation cancels), ExpRelu, CTA sum. Last CTA (atomic counter) sums the 800
// partials in fixed index order -> deterministic scalar, resets the counter.
// ---------------------------------------------------------------------------
__global__ void __launch_bounds__(THREADS) reduce_kernel(
    const float* __restrict__ poses,
    const float* __restrict__ wpts,
    const float* __restrict__ boundary,
    const float* __restrict__ nrms,      // [3,N] global normals
    float* __restrict__ out)
{
    const int warp = threadIdx.x >> 5;
    const int lane = threadIdx.x & 31;
    const int qid  = blockIdx.x * 8 + warp;

    // All lanes recompute the query (broadcast loads, identical fmaf chain)
    float nwx, nwy, nwz;
    query_transform(poses, wpts, qid, nwx, nwy, nwz);

    float vmin = FLT_MAX;
    int   s0   = 0x7FFFFFFF;
    if (lane < NCH) {
        vmin = g_pmin[qid * NCH + lane];
        s0   = g_ps0 [qid * NCH + lane];
    }
    #pragma unroll
    for (int off = 16; off > 0; off >>= 1) {
        float v2 = __shfl_xor_sync(0xFFFFFFFFu, vmin, off);
        int   s2 = __shfl_xor_sync(0xFFFFFFFFu, s0,   off);
        if (v2 < vmin || (v2 == vmin && s2 < s0)) { vmin = v2; s0 = s2; }
    }

    // Rescan 160-pt range from boundary (coalesced); exact-equality recovery.
    const int ch   = s0 / CH_PAD;
    const int offb = s0 - ch * CH_PAD;            // 0..1279 within chunk
    int nbest = 0x7FFFFFFF;
    #pragma unroll
    for (int k = lane; k < RANGE; k += 32) {
        const int o = offb + k;
        if (o < CH_PTS) {
            const int n = ch * CH_PTS + o;
            float x = boundary[0 * NN + n];
            float y = boundary[1 * NN + n];
            float z = boundary[2 * NN + n];
            float c = 0.5f * fmaf(x, x, fmaf(y, y, z * z));
            float q = fmaf(nwx, x, fmaf(nwy, y, fmaf(nwz, z, c)));
            if (q == vmin && n < nbest) nbest = n;
        }
    }
    #pragma unroll
    for (int off = 16; off > 0; off >>= 1)
        nbest = min(nbest, __shfl_xor_sync(0xFFFFFFFFu, nbest, off));

    __shared__ float sh[8];
    if (lane == 0) {
        const int n = nbest;
        const float cpx = boundary[0 * NN + n];
        const float cpy = boundary[1 * NN + n];
        const float cpz = boundary[2 * NN + n];
        const float nx  = nrms[0 * NN + n];
        const float ny  = nrms[1 * NN + n];
        const float nz  = nrms[2 * NN + n];
        // global-frame dot: (wg - cp) . n_g  (rigid transform cancels)
        const float d = (-nwx - cpx) * nx + (-nwy - cpy) * ny + (-nwz - cpz) * nz;
        sh[warp] = (d > 0.0f) ? (d + 1.0f) : expf(0.5f * d);  // ExpRelu a=1,b=.5
    }
    __syncthreads();

    __shared__ int s_last;
    if (threadIdx.x == 0) {
        float s = 0.0f;
        #pragma unroll
        for (int w = 0; w < 8; ++w) s += sh[w];
        g_part[blockIdx.x] = s;
        __threadfence();
        const int old = atomicAdd(&g_cnt, 1);
        s_last = (old == NRED - 1) ? 1 : 0;
    }
    __syncthreads();

    if (s_last) {
        // Last CTA: deterministic fixed-order sum of all 800 partials.
        __shared__ float acc[THREADS];
        const int tid = threadIdx.x;
        float s = 0.0f;
        for (int k = tid; k < NRED; k += THREADS) s += g_part[k];
        acc[tid] = s;
        __syncthreads();
        #pragma unroll
        for (int o = THREADS / 2; o > 0; o >>= 1) {
            if (tid < o) acc[tid] += acc[tid + o];
            __syncthreads();
        }
        if (tid == 0) {
            out[0] = acc[0] * (1.0f / (float)NQ);
            g_cnt = 0;   // replay-safe reset
        }
    }
}

// ---------------------------------------------------------------------------
extern "C" void kernel_launch(void* const* d_in, const int* in_sizes, int n_in,
                              void* d_out, int out_size)
{
    const float* poses    = (const float*)d_in[0];  // [64,4,4]
    const float* wpts     = (const float*)d_in[1];  // [64,100,3]
    const float* boundary = (const float*)d_in[2];  // [4,20000]
    const float* nrms     = (const float*)d_in[3];  // [3,20000]
    float* out = (float*)d_out;

    dim3 gridn(NCH, NTILE);
    nn_kernel<<<gridn, THREADS>>>(poses, wpts, boundary);
    reduce_kernel<<<NRED, THREADS>>>(poses, wpts, boundary, nrms, out);
}